// round 12
// baseline (speedup 1.0000x reference)
#include <cuda_runtime.h>
#include <math.h>
#include <stdint.h>

#define NN   50000
#define EE   800000
#define IN_F 30
#define HH   8
#define DD   32
#define GG   512
#define HIDN 128
#define F1   256            // H*D

// ---------------- device scratch (no allocation allowed) ----------------
__device__ float g_feat1[NN * F1];
__device__ float g_out1 [NN * F1];   // layer-1 seed: x@resW1 + b1
__device__ float g_h1   [NN * F1];
__device__ float g_feat2[NN * F1];
__device__ float g_el1[NN * HH], g_er1[NN * HH];
__device__ float g_el2[NN * HH], g_er2[NN * HH];
__device__ float g_gsum[GG * DD], g_gmax[GG * DD];
// CSR-by-dst
__device__ int g_cnt[NN];
__device__ int g_rowptr[NN + 1];
__device__ int g_cursor[NN];
__device__ int g_csrc[EE];

__device__ __forceinline__ void atomicMaxF(float* addr, float v) {
    if (v >= 0.0f) atomicMax((int*)addr, __float_as_int(v));
    else           atomicMin((unsigned int*)addr, __float_as_uint(v));
}

__device__ __forceinline__ uint32_t f2tf32(float f) {
    uint32_t r;
    asm("cvt.rna.tf32.f32 %0, %1;" : "=r"(r) : "f"(f));
    return r;
}

__device__ __forceinline__ void mma_tf32(float* c, const uint32_t* a, const uint32_t* b) {
    asm volatile(
        "mma.sync.aligned.m16n8k8.row.col.f32.tf32.tf32.f32 "
        "{%0,%1,%2,%3}, {%4,%5,%6,%7}, {%8,%9}, {%0,%1,%2,%3};"
        : "+f"(c[0]), "+f"(c[1]), "+f"(c[2]), "+f"(c[3])
        : "r"(a[0]), "r"(a[1]), "r"(a[2]), "r"(a[3]), "r"(b[0]), "r"(b[1]));
}

__device__ __forceinline__ float expw(float e) {
    e = e > 0.f ? e : 0.2f * e;
    return __expf(e);
}

// ---------------- Stage A: layer-1 projection + attention dots + inits ----
__global__ void __launch_bounds__(256) kA(
    const float* __restrict__ x, const float* __restrict__ W1,
    const float* __restrict__ resW1, const float* __restrict__ b1,
    const float* __restrict__ al1, const float* __restrict__ ar1)
{
    int n = blockIdx.x;
    int t = threadIdx.x;
    __shared__ float xs[IN_F];
    if (t < IN_F) xs[t] = x[n * IN_F + t];
    if (t == 0) g_cnt[n] = 0;
    __syncthreads();

    float f = 0.f, r = 0.f;
#pragma unroll
    for (int k = 0; k < IN_F; k++) {
        float xv = xs[k];
        f += xv * W1[k * F1 + t];
        r += xv * resW1[k * F1 + t];
    }
    g_feat1[n * F1 + t] = f;
    g_out1[n * F1 + t]  = r + b1[t];

    int h = t >> 5, lane = t & 31;
    float elv = f * al1[h * DD + lane];
    float erv = f * ar1[h * DD + lane];
#pragma unroll
    for (int o = 16; o > 0; o >>= 1) {
        elv += __shfl_down_sync(0xffffffffu, elv, o);
        erv += __shfl_down_sync(0xffffffffu, erv, o);
    }
    if (lane == 0) { g_el1[n * HH + h] = elv; g_er1[n * HH + h] = erv; }

    int gid = n * F1 + t;
    if (gid < GG * DD) { g_gsum[gid] = 0.f; g_gmax[gid] = -INFINITY; }
}

// ---------------- CSR build: histogram ------------------------------------
__global__ void __launch_bounds__(256) kHist(const int* __restrict__ dst)
{
    int e = blockIdx.x * 256 + threadIdx.x;
    if (e < EE) atomicAdd(&g_cnt[dst[e]], 1);
}

// ---------------- CSR build: single-block exclusive scan ------------------
__global__ void __launch_bounds__(1024) kScan()
{
    __shared__ int warpsum[32];
    __shared__ int s_run;
    int t = threadIdx.x, lane = t & 31, wid = t >> 5;
    if (t == 0) s_run = 0;
    __syncthreads();
    for (int base = 0; base < NN; base += 1024) {
        int idx = base + t;
        int v = (idx < NN) ? g_cnt[idx] : 0;
        int x = v;
#pragma unroll
        for (int o = 1; o < 32; o <<= 1) {
            int y = __shfl_up_sync(0xffffffffu, x, o);
            if (lane >= o) x += y;
        }
        if (lane == 31) warpsum[wid] = x;
        __syncthreads();
        if (wid == 0) {
            int y = warpsum[lane];
#pragma unroll
            for (int o = 1; o < 32; o <<= 1) {
                int z = __shfl_up_sync(0xffffffffu, y, o);
                if (lane >= o) y += z;
            }
            warpsum[lane] = y;
        }
        __syncthreads();
        int excl = x - v + (wid > 0 ? warpsum[wid - 1] : 0) + s_run;
        if (idx < NN) { g_rowptr[idx] = excl; g_cursor[idx] = excl; }
        __syncthreads();
        if (t == 0) s_run += warpsum[31];
        __syncthreads();
    }
    if (t == 0) g_rowptr[NN] = s_run;
}

// ---------------- CSR build: scatter src by dst ---------------------------
__global__ void __launch_bounds__(256) kScatter(
    const int* __restrict__ src, const int* __restrict__ dst)
{
    int e = blockIdx.x * 256 + threadIdx.x;
    if (e >= EE) return;
    int pos = atomicAdd(&g_cursor[dst[e]], 1);
    g_csrc[pos] = src[e];
}

// ---------------- Warp-per-node fused GAT layer (two-phase tiles) ---------
// Phase 1: lane j computes 8 head weights of edge j into smem (expf on all
//          32 lanes), denominators via xor-shuffle reduce.
// Phase 2: per-edge LDS weights + 2 feat LDG per lane, high MLP.
__global__ void __launch_bounds__(256) kNodeW(
    int layer, const float* __restrict__ b2,
    const int* __restrict__ gids, const float* __restrict__ Ww,
    const float* __restrict__ bw)
{
    __shared__ float sh_w[8][32 * 8];
    __shared__ int   sh_sj[8][32];

    int wid = threadIdx.x >> 5;
    int n = blockIdx.x * 8 + wid;
    if (n >= NN) return;
    int lane = threadIdx.x & 31;

    const float* feat = layer ? g_feat2 : g_feat1;
    const float* el   = layer ? g_el2   : g_el1;
    const float* er   = layer ? g_er2   : g_er1;

    int r0  = g_rowptr[n];
    int deg = g_rowptr[n + 1] - r0;

    // broadcast-load full er vector for this node
    float4 er03 = *(const float4*)(er + n * HH);
    float4 er47 = *(const float4*)(er + n * HH + 4);

    int h0 = lane >> 3, h1 = 4 + (lane >> 3);

    float4 a0 = make_float4(0.f, 0.f, 0.f, 0.f);
    float4 a1 = make_float4(0.f, 0.f, 0.f, 0.f);
    float4 ss03 = make_float4(0.f, 0.f, 0.f, 0.f);
    float4 ss47 = make_float4(0.f, 0.f, 0.f, 0.f);

    for (int base = 0; base < deg; base += 32) {
        int cnt = min(32, deg - base);
        // ---- phase 1: per-lane edge weight computation ----
        float4 w03 = make_float4(0.f, 0.f, 0.f, 0.f);
        float4 w47 = make_float4(0.f, 0.f, 0.f, 0.f);
        int sj_l = 0;
        if (lane < cnt) {
            sj_l = g_csrc[r0 + base + lane];
            float4 el03 = *(const float4*)(el + sj_l * HH);
            float4 el47 = *(const float4*)(el + sj_l * HH + 4);
            w03.x = expw(el03.x + er03.x); w03.y = expw(el03.y + er03.y);
            w03.z = expw(el03.z + er03.z); w03.w = expw(el03.w + er03.w);
            w47.x = expw(el47.x + er47.x); w47.y = expw(el47.y + er47.y);
            w47.z = expw(el47.z + er47.z); w47.w = expw(el47.w + er47.w);
        }
        sh_sj[wid][lane] = sj_l;
        *(float4*)&sh_w[wid][lane * 8]     = w03;
        *(float4*)&sh_w[wid][lane * 8 + 4] = w47;
        // denominator: reduce the 8-vector across lanes
        float4 s03 = w03, s47 = w47;
#pragma unroll
        for (int off = 16; off > 0; off >>= 1) {
            s03.x += __shfl_xor_sync(0xffffffffu, s03.x, off);
            s03.y += __shfl_xor_sync(0xffffffffu, s03.y, off);
            s03.z += __shfl_xor_sync(0xffffffffu, s03.z, off);
            s03.w += __shfl_xor_sync(0xffffffffu, s03.w, off);
            s47.x += __shfl_xor_sync(0xffffffffu, s47.x, off);
            s47.y += __shfl_xor_sync(0xffffffffu, s47.y, off);
            s47.z += __shfl_xor_sync(0xffffffffu, s47.z, off);
            s47.w += __shfl_xor_sync(0xffffffffu, s47.w, off);
        }
        ss03.x += s03.x; ss03.y += s03.y; ss03.z += s03.z; ss03.w += s03.w;
        ss47.x += s47.x; ss47.y += s47.y; ss47.z += s47.z; ss47.w += s47.w;
        __syncwarp();
        // ---- phase 2: aggregation (independent loads, high MLP) ----
#pragma unroll 8
        for (int j = 0; j < cnt; j++) {
            int sj = sh_sj[wid][j];
            float w0 = sh_w[wid][j * 8 + h0];
            float w1 = sh_w[wid][j * 8 + h1];
            const float4* fp = (const float4*)(feat + (size_t)sj * F1);
            float4 f0 = fp[lane];
            float4 f1 = fp[lane + 32];
            a0.x += w0 * f0.x; a0.y += w0 * f0.y;
            a0.z += w0 * f0.z; a0.w += w0 * f0.w;
            a1.x += w1 * f1.x; a1.y += w1 * f1.y;
            a1.z += w1 * f1.z; a1.w += w1 * f1.w;
        }
        __syncwarp();
    }

    // select this lane's two head denominators
    float s0 = (h0 == 0) ? ss03.x : (h0 == 1) ? ss03.y : (h0 == 2) ? ss03.z : ss03.w;
    float s1 = (h0 == 0) ? ss47.x : (h0 == 1) ? ss47.y : (h0 == 2) ? ss47.z : ss47.w;
    float i0 = 1.f / fmaxf(s0, 1e-9f);
    float i1 = 1.f / fmaxf(s1, 1e-9f);

    if (layer == 0) {
        const float4* sp = (const float4*)(g_out1 + (size_t)n * F1);
        float4 s0v = sp[lane], s1v = sp[lane + 32];
        float4 o0, o1;
        o0.x = s0v.x + a0.x * i0; o0.y = s0v.y + a0.y * i0;
        o0.z = s0v.z + a0.z * i0; o0.w = s0v.w + a0.w * i0;
        o1.x = s1v.x + a1.x * i1; o1.y = s1v.y + a1.y * i1;
        o1.z = s1v.z + a1.z * i1; o1.w = s1v.w + a1.w * i1;
        o0.x = o0.x > 0.f ? o0.x : expm1f(o0.x);
        o0.y = o0.y > 0.f ? o0.y : expm1f(o0.y);
        o0.z = o0.z > 0.f ? o0.z : expm1f(o0.z);
        o0.w = o0.w > 0.f ? o0.w : expm1f(o0.w);
        o1.x = o1.x > 0.f ? o1.x : expm1f(o1.x);
        o1.y = o1.y > 0.f ? o1.y : expm1f(o1.y);
        o1.z = o1.z > 0.f ? o1.z : expm1f(o1.z);
        o1.w = o1.w > 0.f ? o1.w : expm1f(o1.w);
        float4* dp = (float4*)(g_h1 + (size_t)n * F1);
        dp[lane] = o0; dp[lane + 32] = o1;
    } else {
        const float4* bp = (const float4*)b2;
        const float4* hp = (const float4*)(g_h1 + (size_t)n * F1);
        float4 b0 = bp[lane], b1v = bp[lane + 32];
        float4 hh0 = hp[lane], hh1 = hp[lane + 32];
        float4 o0, o1;
        o0.x = b0.x + hh0.x + a0.x * i0; o0.y = b0.y + hh0.y + a0.y * i0;
        o0.z = b0.z + hh0.z + a0.z * i0; o0.w = b0.w + hh0.w + a0.w * i0;
        o1.x = b1v.x + hh1.x + a1.x * i1; o1.y = b1v.y + hh1.y + a1.y * i1;
        o1.z = b1v.z + hh1.z + a1.z * i1; o1.w = b1v.w + hh1.w + a1.w * i1;
        float4 s2;
        s2.x = o0.x + o1.x; s2.y = o0.y + o1.y;
        s2.z = o0.z + o1.z; s2.w = o0.w + o1.w;
#pragma unroll
        for (int off = 8; off <= 16; off <<= 1) {
            s2.x += __shfl_xor_sync(0xffffffffu, s2.x, off);
            s2.y += __shfl_xor_sync(0xffffffffu, s2.y, off);
            s2.z += __shfl_xor_sync(0xffffffffu, s2.z, off);
            s2.w += __shfl_xor_sync(0xffffffffu, s2.w, off);
        }
        float4 h2;
        h2.x = s2.x * 0.125f + 0.0f; h2.y = s2.y * 0.125f + 0.0f;
        h2.z = s2.z * 0.125f + 0.0f; h2.w = s2.w * 0.125f + 0.0f;
        int d0 = 4 * (lane & 7);
        float part = 0.f;
        if (lane < 8)
            part = h2.x * Ww[d0] + h2.y * Ww[d0 + 1]
                 + h2.z * Ww[d0 + 2] + h2.w * Ww[d0 + 3];
#pragma unroll
        for (int off = 16; off > 0; off >>= 1)
            part += __shfl_xor_sync(0xffffffffu, part, off);
        float w = 1.f / (1.f + __expf(-(part + bw[0])));
        if (lane < 8) {
            int g = gids[n];
            float* gsp = &g_gsum[g * DD + d0];
            atomicAdd(gsp + 0, w * h2.x);
            atomicAdd(gsp + 1, w * h2.y);
            atomicAdd(gsp + 2, w * h2.z);
            atomicAdd(gsp + 3, w * h2.w);
            float* gmp = &g_gmax[g * DD + d0];
            atomicMaxF(gmp + 0, h2.x);
            atomicMaxF(gmp + 1, h2.y);
            atomicMaxF(gmp + 2, h2.z);
            atomicMaxF(gmp + 3, h2.w);
        }
    }
}

// ---------------- tf32 mma.sync GEMM: feat2 = h1 @ W2, fused el2/er2 ------
#define AS_STRIDE 36
#define BS_STRIDE 136
__global__ void __launch_bounds__(256) kGemmMMA(
    const float* __restrict__ W2,
    const float* __restrict__ al2, const float* __restrict__ ar2)
{
    __shared__ uint32_t as_[128 * AS_STRIDE];
    __shared__ uint32_t bs_[32 * BS_STRIDE];
    __shared__ float sal[128], sar[128];

    int t = threadIdx.x;
    int lane = t & 31, warp = t >> 5;
    int gid = lane >> 2, tid4 = lane & 3;
    int wm = warp >> 1, wn = warp & 1;

    int row0 = blockIdx.x * 128;
    int c0   = blockIdx.y * 128;

    if (t < 128) { sal[t] = al2[c0 + t]; sar[t] = ar2[c0 + t]; }

    float acc[2][8][4];
#pragma unroll
    for (int i = 0; i < 2; i++)
#pragma unroll
        for (int j = 0; j < 8; j++)
#pragma unroll
            for (int q = 0; q < 4; q++) acc[i][j][q] = 0.f;

    for (int s = 0; s < 8; s++) {
#pragma unroll
        for (int q = 0; q < 4; q++) {
            int p = t + q * 256;
            int r = p >> 3, c4 = p & 7;
            float4 v = (row0 + r < NN)
                ? *(const float4*)(g_h1 + (size_t)(row0 + r) * F1 + s * 32 + c4 * 4)
                : make_float4(0.f, 0.f, 0.f, 0.f);
            uint32_t* dstp = &as_[r * AS_STRIDE + c4 * 4];
            dstp[0] = f2tf32(v.x); dstp[1] = f2tf32(v.y);
            dstp[2] = f2tf32(v.z); dstp[3] = f2tf32(v.w);
        }
#pragma unroll
        for (int q = 0; q < 4; q++) {
            int p = t + q * 256;
            int r = p >> 5, c4 = p & 31;
            float4 v = *(const float4*)(W2 + (size_t)(s * 32 + r) * F1 + c0 + c4 * 4);
            uint32_t* dstp = &bs_[r * BS_STRIDE + c4 * 4];
            dstp[0] = f2tf32(v.x); dstp[1] = f2tf32(v.y);
            dstp[2] = f2tf32(v.z); dstp[3] = f2tf32(v.w);
        }
        __syncthreads();

#pragma unroll
        for (int kk = 0; kk < 4; kk++) {
            uint32_t bf[8][2];
            int kb = kk * 8 + tid4;
#pragma unroll
            for (int j = 0; j < 8; j++) {
                int nn = wn * 64 + j * 8 + gid;
                bf[j][0] = bs_[kb * BS_STRIDE + nn];
                bf[j][1] = bs_[(kb + 4) * BS_STRIDE + nn];
            }
#pragma unroll
            for (int i = 0; i < 2; i++) {
                uint32_t af[4];
                int m = wm * 32 + i * 16 + gid;
                af[0] = as_[m * AS_STRIDE + kk * 8 + tid4];
                af[1] = as_[(m + 8) * AS_STRIDE + kk * 8 + tid4];
                af[2] = as_[m * AS_STRIDE + kk * 8 + tid4 + 4];
                af[3] = as_[(m + 8) * AS_STRIDE + kk * 8 + tid4 + 4];
#pragma unroll
                for (int j = 0; j < 8; j++) mma_tf32(acc[i][j], af, bf[j]);
            }
        }
        __syncthreads();
    }

#pragma unroll
    for (int i = 0; i < 2; i++) {
        int mrow = row0 + wm * 32 + i * 16 + gid;
        float elv[2][2] = {{0.f, 0.f}, {0.f, 0.f}};
        float erv[2][2] = {{0.f, 0.f}, {0.f, 0.f}};
#pragma unroll
        for (int j = 0; j < 8; j++) {
            int nl = wn * 64 + j * 8 + tid4 * 2;
            int hl = j >> 2;
            float* cc = acc[i][j];
            float w0l = sal[nl], w1l = sal[nl + 1];
            float w0r = sar[nl], w1r = sar[nl + 1];
            if (mrow < NN)
                *(float2*)(g_feat2 + (size_t)mrow * F1 + c0 + nl) =
                    make_float2(cc[0], cc[1]);
            if (mrow + 8 < NN)
                *(float2*)(g_feat2 + (size_t)(mrow + 8) * F1 + c0 + nl) =
                    make_float2(cc[2], cc[3]);
            elv[0][hl] += cc[0] * w0l + cc[1] * w1l;
            elv[1][hl] += cc[2] * w0l + cc[3] * w1l;
            erv[0][hl] += cc[0] * w0r + cc[1] * w1r;
            erv[1][hl] += cc[2] * w0r + cc[3] * w1r;
        }
#pragma unroll
        for (int off = 1; off < 4; off <<= 1) {
#pragma unroll
            for (int rh = 0; rh < 2; rh++)
#pragma unroll
                for (int hl = 0; hl < 2; hl++) {
                    elv[rh][hl] += __shfl_xor_sync(0xffffffffu, elv[rh][hl], off);
                    erv[rh][hl] += __shfl_xor_sync(0xffffffffu, erv[rh][hl], off);
                }
        }
        if (tid4 == 0) {
            int hbase = (c0 >> 5) + wn * 2;
            if (mrow < NN) {
                g_el2[mrow * HH + hbase]     = elv[0][0];
                g_el2[mrow * HH + hbase + 1] = elv[0][1];
                g_er2[mrow * HH + hbase]     = erv[0][0];
                g_er2[mrow * HH + hbase + 1] = erv[0][1];
            }
            if (mrow + 8 < NN) {
                g_el2[(mrow + 8) * HH + hbase]     = elv[1][0];
                g_el2[(mrow + 8) * HH + hbase + 1] = elv[1][1];
                g_er2[(mrow + 8) * HH + hbase]     = erv[1][0];
                g_er2[(mrow + 8) * HH + hbase + 1] = erv[1][1];
            }
        }
    }
}

// ---------------- Stage H: MLP predictor ----------------------------------
__global__ void __launch_bounds__(128) kH(
    const float* __restrict__ Wp1, const float* __restrict__ bp1,
    const float* __restrict__ gamma, const float* __restrict__ beta,
    const float* __restrict__ rm, const float* __restrict__ rv,
    const float* __restrict__ Wp2, const float* __restrict__ bp2,
    float* __restrict__ outp)
{
    int g = blockIdx.x, t = threadIdx.x;
    __shared__ float gs[64];
    __shared__ float wsum[4];
    if (t < 32) gs[t] = g_gsum[g * DD + t];
    else if (t < 64) {
        float mv = g_gmax[g * DD + (t - 32)];
        if (!isfinite(mv)) mv = 0.f;
        gs[t] = mv;
    }
    __syncthreads();
    float acc = bp1[t];
#pragma unroll
    for (int k = 0; k < 64; k++) acc += gs[k] * Wp1[k * HIDN + t];
    acc = fmaxf(acc, 0.f);
    acc = (acc - rm[t]) * rsqrtf(rv[t] + 1e-5f) * gamma[t] + beta[t];
    float v = acc * Wp2[t];
#pragma unroll
    for (int o = 16; o > 0; o >>= 1) v += __shfl_xor_sync(0xffffffffu, v, o);
    if ((t & 31) == 0) wsum[t >> 5] = v;
    __syncthreads();
    if (t == 0) outp[g] = wsum[0] + wsum[1] + wsum[2] + wsum[3] + bp2[0];
}

// ---------------- launcher ------------------------------------------------
extern "C" void kernel_launch(void* const* d_in, const int* in_sizes, int n_in,
                              void* d_out, int out_size)
{
    const float* x     = (const float*)d_in[0];
    const int*   src   = (const int*)  d_in[1];
    const int*   dst   = (const int*)  d_in[2];
    const int*   gids  = (const int*)  d_in[3];
    const float* W1    = (const float*)d_in[4];
    const float* al1   = (const float*)d_in[5];
    const float* ar1   = (const float*)d_in[6];
    const float* b1    = (const float*)d_in[7];
    const float* resW1 = (const float*)d_in[8];
    const float* W2    = (const float*)d_in[9];
    const float* al2   = (const float*)d_in[10];
    const float* ar2   = (const float*)d_in[11];
    const float* b2    = (const float*)d_in[12];
    const float* Ww    = (const float*)d_in[13];
    const float* bw    = (const float*)d_in[14];
    const float* Wp1   = (const float*)d_in[15];
    const float* bp1   = (const float*)d_in[16];
    const float* gamma = (const float*)d_in[17];
    const float* beta  = (const float*)d_in[18];
    const float* rm    = (const float*)d_in[19];
    const float* rv    = (const float*)d_in[20];
    const float* Wp2   = (const float*)d_in[21];
    const float* bp2   = (const float*)d_in[22];
    float* outp = (float*)d_out;

    int eb = (EE + 255) / 256;

    kA<<<NN, 256>>>(x, W1, resW1, b1, al1, ar1);
    kHist<<<eb, 256>>>(dst);
    kScan<<<1, 1024>>>();
    kScatter<<<eb, 256>>>(src, dst);
    kNodeW<<<(NN + 7) / 8, 256>>>(0, b2, gids, Ww, bw);
    dim3 gg((NN + 127) / 128, 2);
    kGemmMMA<<<gg, 256>>>(W2, al2, ar2);
    kNodeW<<<(NN + 7) / 8, 256>>>(1, b2, gids, Ww, bw);
    kH<<<GG, 128>>>(Wp1, bp1, gamma, beta, rm, rv, Wp2, bp2, outp);
}

// round 15
// speedup vs baseline: 1.1731x; 1.1731x over previous
#include <cuda_runtime.h>
#include <cuda_fp16.h>
#include <math.h>
#include <stdint.h>

#define NN   50000
#define EE   800000
#define IN_F 30
#define HH   8
#define DD   32
#define GG   512
#define HIDN 128
#define F1   256            // H*D

// ---------------- device scratch (no allocation allowed) ----------------
__device__ __half g_feat1h[NN * F1];   // fp16 gather features, layer 1
__device__ __half g_feat2h[NN * F1];   // fp16 gather features, layer 2
__device__ float g_out1 [NN * F1];     // layer-1 seed: x@resW1 + b1
__device__ float g_h1   [NN * F1];
__device__ float g_el1[NN * HH], g_er1[NN * HH];
__device__ float g_el2[NN * HH], g_er2[NN * HH];
__device__ float g_gsum[GG * DD], g_gmax[GG * DD];
// CSR-by-dst
__device__ int g_cnt[NN];
__device__ int g_rowptr[NN + 1];
__device__ int g_cursor[NN];
__device__ int g_csrc[EE];

__device__ __forceinline__ void atomicMaxF(float* addr, float v) {
    if (v >= 0.0f) atomicMax((int*)addr, __float_as_int(v));
    else           atomicMin((unsigned int*)addr, __float_as_uint(v));
}

__device__ __forceinline__ uint32_t f2tf32(float f) {
    uint32_t r;
    asm("cvt.rna.tf32.f32 %0, %1;" : "=r"(r) : "f"(f));
    return r;
}

__device__ __forceinline__ void mma_tf32(float* c, const uint32_t* a, const uint32_t* b) {
    asm volatile(
        "mma.sync.aligned.m16n8k8.row.col.f32.tf32.tf32.f32 "
        "{%0,%1,%2,%3}, {%4,%5,%6,%7}, {%8,%9}, {%0,%1,%2,%3};"
        : "+f"(c[0]), "+f"(c[1]), "+f"(c[2]), "+f"(c[3])
        : "r"(a[0]), "r"(a[1]), "r"(a[2]), "r"(a[3]), "r"(b[0]), "r"(b[1]));
}

__device__ __forceinline__ float expw(float e) {
    e = e > 0.f ? e : 0.2f * e;
    return __expf(e);
}

// ---------------- Stage A: layer-1 projection + attention dots + inits ----
__global__ void __launch_bounds__(256) kA(
    const float* __restrict__ x, const float* __restrict__ W1,
    const float* __restrict__ resW1, const float* __restrict__ b1,
    const float* __restrict__ al1, const float* __restrict__ ar1)
{
    int n = blockIdx.x;
    int t = threadIdx.x;
    __shared__ float xs[IN_F];
    if (t < IN_F) xs[t] = x[n * IN_F + t];
    if (t == 0) g_cnt[n] = 0;
    __syncthreads();

    float f = 0.f, r = 0.f;
#pragma unroll
    for (int k = 0; k < IN_F; k++) {
        float xv = xs[k];
        f += xv * W1[k * F1 + t];
        r += xv * resW1[k * F1 + t];
    }
    g_feat1h[(size_t)n * F1 + t] = __float2half(f);
    g_out1[n * F1 + t]  = r + b1[t];

    int h = t >> 5, lane = t & 31;
    float elv = f * al1[h * DD + lane];
    float erv = f * ar1[h * DD + lane];
#pragma unroll
    for (int o = 16; o > 0; o >>= 1) {
        elv += __shfl_down_sync(0xffffffffu, elv, o);
        erv += __shfl_down_sync(0xffffffffu, erv, o);
    }
    if (lane == 0) { g_el1[n * HH + h] = elv; g_er1[n * HH + h] = erv; }

    int gid = n * F1 + t;
    if (gid < GG * DD) { g_gsum[gid] = 0.f; g_gmax[gid] = -INFINITY; }
}

// ---------------- CSR build: histogram ------------------------------------
__global__ void __launch_bounds__(256) kHist(const int* __restrict__ dst)
{
    int e = blockIdx.x * 256 + threadIdx.x;
    if (e < EE) atomicAdd(&g_cnt[dst[e]], 1);
}

// ---------------- CSR build: single-block exclusive scan ------------------
__global__ void __launch_bounds__(1024) kScan()
{
    __shared__ int warpsum[32];
    __shared__ int s_run;
    int t = threadIdx.x, lane = t & 31, wid = t >> 5;
    if (t == 0) s_run = 0;
    __syncthreads();
    for (int base = 0; base < NN; base += 1024) {
        int idx = base + t;
        int v = (idx < NN) ? g_cnt[idx] : 0;
        int x = v;
#pragma unroll
        for (int o = 1; o < 32; o <<= 1) {
            int y = __shfl_up_sync(0xffffffffu, x, o);
            if (lane >= o) x += y;
        }
        if (lane == 31) warpsum[wid] = x;
        __syncthreads();
        if (wid == 0) {
            int y = warpsum[lane];
#pragma unroll
            for (int o = 1; o < 32; o <<= 1) {
                int z = __shfl_up_sync(0xffffffffu, y, o);
                if (lane >= o) y += z;
            }
            warpsum[lane] = y;
        }
        __syncthreads();
        int excl = x - v + (wid > 0 ? warpsum[wid - 1] : 0) + s_run;
        if (idx < NN) { g_rowptr[idx] = excl; g_cursor[idx] = excl; }
        __syncthreads();
        if (t == 0) s_run += warpsum[31];
        __syncthreads();
    }
    if (t == 0) g_rowptr[NN] = s_run;
}

// ---------------- CSR build: scatter src by dst ---------------------------
__global__ void __launch_bounds__(256) kScatter(
    const int* __restrict__ src, const int* __restrict__ dst)
{
    int e = blockIdx.x * 256 + threadIdx.x;
    if (e >= EE) return;
    int pos = atomicAdd(&g_cursor[dst[e]], 1);
    g_csrc[pos] = src[e];
}

// ---------------- Warp-per-node fused GAT layer (fp16 gather) -------------
// Lane L owns feats 8L..8L+7 (16B, ONE uint4 load/edge), all in head L>>2.
// Denominator per head comes free: sw accumulates this lane's head weight.
__global__ void __launch_bounds__(256) kNodeW(
    int layer, const float* __restrict__ b2,
    const int* __restrict__ gids, const float* __restrict__ Ww,
    const float* __restrict__ bw)
{
    int n = blockIdx.x * 8 + (threadIdx.x >> 5);
    if (n >= NN) return;
    int lane = threadIdx.x & 31;

    const __half* feat = layer ? g_feat2h : g_feat1h;
    const float* el    = layer ? g_el2    : g_el1;
    const float* er    = layer ? g_er2    : g_er1;

    int r0  = g_rowptr[n];
    int deg = g_rowptr[n + 1] - r0;

    float er_l = (lane < 8) ? er[n * HH + lane] : 0.f;
    int hsel = lane >> 2;

    float a[8];
#pragma unroll
    for (int k = 0; k < 8; k++) a[k] = 0.f;
    float sw = 0.f;

    for (int base = 0; base < deg; base += 32) {
        int cnt = min(32, deg - base);
        int sj_l = (lane < cnt) ? g_csrc[r0 + base + lane] : 0;
#pragma unroll 4
        for (int j = 0; j < cnt; j++) {
            int sj = __shfl_sync(0xffffffffu, sj_l, j);
            float ev = 0.f;
            if (lane < 8) ev = expw(el[sj * HH + lane] + er_l);
            float w = __shfl_sync(0xffffffffu, ev, hsel);
            sw += w;
            uint4 v = *(const uint4*)(feat + (size_t)sj * F1 + lane * 8);
            __half2* hp = (__half2*)&v;
            float2 f0 = __half22float2(hp[0]);
            float2 f1 = __half22float2(hp[1]);
            float2 f2 = __half22float2(hp[2]);
            float2 f3 = __half22float2(hp[3]);
            a[0] += w * f0.x; a[1] += w * f0.y;
            a[2] += w * f1.x; a[3] += w * f1.y;
            a[4] += w * f2.x; a[5] += w * f2.y;
            a[6] += w * f3.x; a[7] += w * f3.y;
        }
    }

    float inv = 1.f / fmaxf(sw, 1e-9f);

    if (layer == 0) {
        const float4* sp = (const float4*)(g_out1 + (size_t)n * F1 + lane * 8);
        float4 s0 = sp[0], s1 = sp[1];
        float o[8];
        o[0] = s0.x + a[0] * inv; o[1] = s0.y + a[1] * inv;
        o[2] = s0.z + a[2] * inv; o[3] = s0.w + a[3] * inv;
        o[4] = s1.x + a[4] * inv; o[5] = s1.y + a[5] * inv;
        o[6] = s1.z + a[6] * inv; o[7] = s1.w + a[7] * inv;
#pragma unroll
        for (int k = 0; k < 8; k++) o[k] = o[k] > 0.f ? o[k] : expm1f(o[k]);
        float4* dp = (float4*)(g_h1 + (size_t)n * F1 + lane * 8);
        dp[0] = make_float4(o[0], o[1], o[2], o[3]);
        dp[1] = make_float4(o[4], o[5], o[6], o[7]);
    } else {
        const float4* bp = (const float4*)(b2 + lane * 8);
        const float4* hp = (const float4*)(g_h1 + (size_t)n * F1 + lane * 8);
        float4 b0 = bp[0], b1v = bp[1];
        float4 h0 = hp[0], h1v = hp[1];
        float s[8];
        s[0] = b0.x + h0.x + a[0] * inv;  s[1] = b0.y + h0.y + a[1] * inv;
        s[2] = b0.z + h0.z + a[2] * inv;  s[3] = b0.w + h0.w + a[3] * inv;
        s[4] = b1v.x + h1v.x + a[4] * inv; s[5] = b1v.y + h1v.y + a[5] * inv;
        s[6] = b1v.z + h1v.z + a[6] * inv; s[7] = b1v.w + h1v.w + a[7] * inv;
        // head-mean: sum across the 8 heads (lanes differing in bits 2..4)
#pragma unroll
        for (int off = 4; off <= 16; off <<= 1) {
#pragma unroll
            for (int k = 0; k < 8; k++)
                s[k] += __shfl_xor_sync(0xffffffffu, s[k], off);
        }
        float h2[8];
#pragma unroll
        for (int k = 0; k < 8; k++) h2[k] = s[k] * 0.125f + 0.0f;
        int d0 = 8 * (lane & 3);
        float part = 0.f;
#pragma unroll
        for (int k = 0; k < 8; k++) part += h2[k] * Ww[d0 + k];
        part += __shfl_xor_sync(0xffffffffu, part, 1);
        part += __shfl_xor_sync(0xffffffffu, part, 2);
        float w = 1.f / (1.f + __expf(-(part + bw[0])));
        if (lane < 4) {
            int g = gids[n];
            float* gsp = &g_gsum[g * DD + d0];
            float* gmp = &g_gmax[g * DD + d0];
#pragma unroll
            for (int k = 0; k < 8; k++) {
                atomicAdd(gsp + k, w * h2[k]);
                atomicMaxF(gmp + k, h2[k]);
            }
        }
    }
}

// ---------------- tf32 mma.sync GEMM: feat2h = h1 @ W2, fused el2/er2 -----
#define AS_STRIDE 36
#define BS_STRIDE 136
__global__ void __launch_bounds__(256) kGemmMMA(
    const float* __restrict__ W2,
    const float* __restrict__ al2, const float* __restrict__ ar2)
{
    __shared__ uint32_t as_[128 * AS_STRIDE];
    __shared__ uint32_t bs_[32 * BS_STRIDE];
    __shared__ float sal[128], sar[128];

    int t = threadIdx.x;
    int lane = t & 31, warp = t >> 5;
    int gid = lane >> 2, tid4 = lane & 3;
    int wm = warp >> 1, wn = warp & 1;

    int row0 = blockIdx.x * 128;
    int c0   = blockIdx.y * 128;

    if (t < 128) { sal[t] = al2[c0 + t]; sar[t] = ar2[c0 + t]; }

    float acc[2][8][4];
#pragma unroll
    for (int i = 0; i < 2; i++)
#pragma unroll
        for (int j = 0; j < 8; j++)
#pragma unroll
            for (int q = 0; q < 4; q++) acc[i][j][q] = 0.f;

    for (int s = 0; s < 8; s++) {
#pragma unroll
        for (int q = 0; q < 4; q++) {
            int p = t + q * 256;
            int r = p >> 3, c4 = p & 7;
            float4 v = (row0 + r < NN)
                ? *(const float4*)(g_h1 + (size_t)(row0 + r) * F1 + s * 32 + c4 * 4)
                : make_float4(0.f, 0.f, 0.f, 0.f);
            uint32_t* dstp = &as_[r * AS_STRIDE + c4 * 4];
            dstp[0] = f2tf32(v.x); dstp[1] = f2tf32(v.y);
            dstp[2] = f2tf32(v.z); dstp[3] = f2tf32(v.w);
        }
#pragma unroll
        for (int q = 0; q < 4; q++) {
            int p = t + q * 256;
            int r = p >> 5, c4 = p & 31;
            float4 v = *(const float4*)(W2 + (size_t)(s * 32 + r) * F1 + c0 + c4 * 4);
            uint32_t* dstp = &bs_[r * BS_STRIDE + c4 * 4];
            dstp[0] = f2tf32(v.x); dstp[1] = f2tf32(v.y);
            dstp[2] = f2tf32(v.z); dstp[3] = f2tf32(v.w);
        }
        __syncthreads();

#pragma unroll
        for (int kk = 0; kk < 4; kk++) {
            uint32_t bf[8][2];
            int kb = kk * 8 + tid4;
#pragma unroll
            for (int j = 0; j < 8; j++) {
                int nn = wn * 64 + j * 8 + gid;
                bf[j][0] = bs_[kb * BS_STRIDE + nn];
                bf[j][1] = bs_[(kb + 4) * BS_STRIDE + nn];
            }
#pragma unroll
            for (int i = 0; i < 2; i++) {
                uint32_t af[4];
                int m = wm * 32 + i * 16 + gid;
                af[0] = as_[m * AS_STRIDE + kk * 8 + tid4];
                af[1] = as_[(m + 8) * AS_STRIDE + kk * 8 + tid4];
                af[2] = as_[m * AS_STRIDE + kk * 8 + tid4 + 4];
                af[3] = as_[(m + 8) * AS_STRIDE + kk * 8 + tid4 + 4];
#pragma unroll
                for (int j = 0; j < 8; j++) mma_tf32(acc[i][j], af, bf[j]);
            }
        }
        __syncthreads();
    }

#pragma unroll
    for (int i = 0; i < 2; i++) {
        int mrow = row0 + wm * 32 + i * 16 + gid;
        float elv[2][2] = {{0.f, 0.f}, {0.f, 0.f}};
        float erv[2][2] = {{0.f, 0.f}, {0.f, 0.f}};
#pragma unroll
        for (int j = 0; j < 8; j++) {
            int nl = wn * 64 + j * 8 + tid4 * 2;
            int hl = j >> 2;
            float* cc = acc[i][j];
            float w0l = sal[nl], w1l = sal[nl + 1];
            float w0r = sar[nl], w1r = sar[nl + 1];
            if (mrow < NN)
                *(__half2*)(g_feat2h + (size_t)mrow * F1 + c0 + nl) =
                    __floats2half2_rn(cc[0], cc[1]);
            if (mrow + 8 < NN)
                *(__half2*)(g_feat2h + (size_t)(mrow + 8) * F1 + c0 + nl) =
                    __floats2half2_rn(cc[2], cc[3]);
            elv[0][hl] += cc[0] * w0l + cc[1] * w1l;
            elv[1][hl] += cc[2] * w0l + cc[3] * w1l;
            erv[0][hl] += cc[0] * w0r + cc[1] * w1r;
            erv[1][hl] += cc[2] * w0r + cc[3] * w1r;
        }
#pragma unroll
        for (int off = 1; off < 4; off <<= 1) {
#pragma unroll
            for (int rh = 0; rh < 2; rh++)
#pragma unroll
                for (int hl = 0; hl < 2; hl++) {
                    elv[rh][hl] += __shfl_xor_sync(0xffffffffu, elv[rh][hl], off);
                    erv[rh][hl] += __shfl_xor_sync(0xffffffffu, erv[rh][hl], off);
                }
        }
        if (tid4 == 0) {
            int hbase = (c0 >> 5) + wn * 2;
            if (mrow < NN) {
                g_el2[mrow * HH + hbase]     = elv[0][0];
                g_el2[mrow * HH + hbase + 1] = elv[0][1];
                g_er2[mrow * HH + hbase]     = erv[0][0];
                g_er2[mrow * HH + hbase + 1] = erv[0][1];
            }
            if (mrow + 8 < NN) {
                g_el2[(mrow + 8) * HH + hbase]     = elv[1][0];
                g_el2[(mrow + 8) * HH + hbase + 1] = elv[1][1];
                g_er2[(mrow + 8) * HH + hbase]     = erv[1][0];
                g_er2[(mrow + 8) * HH + hbase + 1] = erv[1][1];
            }
        }
    }
}

// ---------------- Stage H: MLP predictor ----------------------------------
__global__ void __launch_bounds__(128) kH(
    const float* __restrict__ Wp1, const float* __restrict__ bp1,
    const float* __restrict__ gamma, const float* __restrict__ beta,
    const float* __restrict__ rm, const float* __restrict__ rv,
    const float* __restrict__ Wp2, const float* __restrict__ bp2,
    float* __restrict__ outp)
{
    int g = blockIdx.x, t = threadIdx.x;
    __shared__ float gs[64];
    __shared__ float wsum[4];
    if (t < 32) gs[t] = g_gsum[g * DD + t];
    else if (t < 64) {
        float mv = g_gmax[g * DD + (t - 32)];
        if (!isfinite(mv)) mv = 0.f;
        gs[t] = mv;
    }
    __syncthreads();
    float acc = bp1[t];
#pragma unroll
    for (int k = 0; k < 64; k++) acc += gs[k] * Wp1[k * HIDN + t];
    acc = fmaxf(acc, 0.f);
    acc = (acc - rm[t]) * rsqrtf(rv[t] + 1e-5f) * gamma[t] + beta[t];
    float v = acc * Wp2[t];
#pragma unroll
    for (int o = 16; o > 0; o >>= 1) v += __shfl_xor_sync(0xffffffffu, v, o);
    if ((t & 31) == 0) wsum[t >> 5] = v;
    __syncthreads();
    if (t == 0) outp[g] = wsum[0] + wsum[1] + wsum[2] + wsum[3] + bp2[0];
}

// ---------------- launcher ------------------------------------------------
extern "C" void kernel_launch(void* const* d_in, const int* in_sizes, int n_in,
                              void* d_out, int out_size)
{
    const float* x     = (const float*)d_in[0];
    const int*   src   = (const int*)  d_in[1];
    const int*   dst   = (const int*)  d_in[2];
    const int*   gids  = (const int*)  d_in[3];
    const float* W1    = (const float*)d_in[4];
    const float* al1   = (const float*)d_in[5];
    const float* ar1   = (const float*)d_in[6];
    const float* b1    = (const float*)d_in[7];
    const float* resW1 = (const float*)d_in[8];
    const float* W2    = (const float*)d_in[9];
    const float* al2   = (const float*)d_in[10];
    const float* ar2   = (const float*)d_in[11];
    const float* b2    = (const float*)d_in[12];
    const float* Ww    = (const float*)d_in[13];
    const float* bw    = (const float*)d_in[14];
    const float* Wp1   = (const float*)d_in[15];
    const float* bp1   = (const float*)d_in[16];
    const float* gamma = (const float*)d_in[17];
    const float* beta  = (const float*)d_in[18];
    const float* rm    = (const float*)d_in[19];
    const float* rv    = (const float*)d_in[20];
    const float* Wp2   = (const float*)d_in[21];
    const float* bp2   = (const float*)d_in[22];
    float* outp = (float*)d_out;

    int eb = (EE + 255) / 256;

    kA<<<NN, 256>>>(x, W1, resW1, b1, al1, ar1);
    kHist<<<eb, 256>>>(dst);
    kScan<<<1, 1024>>>();
    kScatter<<<eb, 256>>>(src, dst);
    kNodeW<<<(NN + 7) / 8, 256>>>(0, b2, gids, Ww, bw);
    dim3 gg((NN + 127) / 128, 2);
    kGemmMMA<<<gg, 256>>>(W2, al2, ar2);
    kNodeW<<<(NN + 7) / 8, 256>>>(1, b2, gids, Ww, bw);
    kH<<<GG, 128>>>(Wp1, bp1, gamma, beta, rm, rv, Wp2, bp2, outp);
}